// round 15
// baseline (speedup 1.0000x reference)
#include <cuda_runtime.h>
#include <cuda_fp16.h>
#include <cstdint>

#define NNODES 100000
#define NEDGES 1600000
#define IN_C 64
#define HID 128
#define OUT_C 64
#define NBT 128            // nodes per MLP tile
#define NTILES ((NNODES + NBT - 1) / NBT)   // 782
#define MLP_THREADS 512
#define SCAN_BLK 1024
#define SCAN_NB ((NNODES + SCAN_BLK - 1) / SCAN_BLK)

// Scratch (static device arrays; heap alloc is forbidden)
__device__ __align__(16) __half g_h2[(size_t)NNODES * OUT_C]; // fp16 h2 table, 12.8 MB
__device__ float g_dinv[NNODES];
__device__ int   g_degi[NNODES];
__device__ int   g_off[NNODES];      // CSR offsets; scatter bumps them to 'end'
__device__ int   g_esrc[NEDGES];
__device__ unsigned long long g_scanstate[SCAN_NB];

// ---------------------------------------------------------------------------
__device__ __forceinline__ int detect_stride(const int* __restrict__ ei, int* s_st) {
    if (threadIdx.x < 32) {
        int z = (ei[2 * threadIdx.x + 1] == 0);
        unsigned m = __ballot_sync(0xFFFFFFFFu, z);
        if (threadIdx.x == 0) *s_st = (m == 0xFFFFFFFFu) ? 2 : 1;
    }
    __syncthreads();
    return *s_st;
}

// Degree histogram; block 0 also zeroes the scan lookback states (ordered
// before k_scan by kernel-boundary dependency).
__global__ __launch_bounds__(256) void k_deg_count(const int* __restrict__ ei) {
    __shared__ int s_st;
    const int st = detect_stride(ei, &s_st);
    if (blockIdx.x == 0 && threadIdx.x < SCAN_NB)
        g_scanstate[threadIdx.x] = 0ULL;
    int e = blockIdx.x * blockDim.x + threadIdx.x;
    if (e < NEDGES) {
        int d = ei[(size_t)NEDGES * st + (size_t)e * st];
        if ((unsigned)d < NNODES) atomicAdd(&g_degi[d], 1);
    }
}

__global__ __launch_bounds__(SCAN_BLK) void k_scan() {
    __shared__ int wsum[32];
    __shared__ int s_total, s_prefix;
    const int t = threadIdx.x;
    const int bid = blockIdx.x;
    const int i = bid * SCAN_BLK + t;
    const int v = (i < NNODES) ? g_degi[i] : 0;
    if (i < NNODES) g_dinv[i] = rsqrtf((float)(v + 1));

    int x = v;
    #pragma unroll
    for (int o = 1; o < 32; o <<= 1) {
        int y = __shfl_up_sync(0xFFFFFFFFu, x, o);
        if ((t & 31) >= o) x += y;
    }
    if ((t & 31) == 31) wsum[t >> 5] = x;
    __syncthreads();
    if (t < 32) {
        int w = wsum[t];
        int xx = w;
        #pragma unroll
        for (int o = 1; o < 32; o <<= 1) {
            int y = __shfl_up_sync(0xFFFFFFFFu, xx, o);
            if (t >= o) xx += y;
        }
        wsum[t] = xx - w;
        if (t == 31) s_total = xx;
    }
    __syncthreads();

    if (t == 0) {
        unsigned long long flag = (bid == 0) ? 2ULL : 1ULL;
        __threadfence();
        *(volatile unsigned long long*)&g_scanstate[bid] =
            (flag << 32) | (unsigned)s_total;
        if (bid == 0) s_prefix = 0;
    }

    if (bid > 0 && t < 32) {
        int running = 0;
        int base = bid - 1;
        for (;;) {
            int j = base - t;
            unsigned long long s;
            if (j >= 0) {
                do { s = *(volatile unsigned long long*)&g_scanstate[j]; }
                while ((s >> 32) == 0);
            } else {
                s = (2ULL << 32);
            }
            int flag = (int)(s >> 32);
            int val  = (int)(s & 0xFFFFFFFFu);
            unsigned pmask = __ballot_sync(0xFFFFFFFFu, flag == 2);
            if (pmask) {
                int stop = __ffs(pmask) - 1;
                int contrib = (t <= stop) ? val : 0;
                #pragma unroll
                for (int o = 16; o >= 1; o >>= 1)
                    contrib += __shfl_down_sync(0xFFFFFFFFu, contrib, o);
                running += __shfl_sync(0xFFFFFFFFu, contrib, 0);
                break;
            } else {
                int contrib = val;
                #pragma unroll
                for (int o = 16; o >= 1; o >>= 1)
                    contrib += __shfl_down_sync(0xFFFFFFFFu, contrib, o);
                running += __shfl_sync(0xFFFFFFFFu, contrib, 0);
                base -= 32;
            }
        }
        if (t == 0) {
            __threadfence();
            *(volatile unsigned long long*)&g_scanstate[bid] =
                (2ULL << 32) | (unsigned)(running + s_total);
            s_prefix = running;
        }
    }
    __syncthreads();

    if (i < NNODES) g_off[i] = (x - v + wsum[t >> 5]) + s_prefix;
}

__global__ __launch_bounds__(256) void k_scatter(const int* __restrict__ ei) {
    __shared__ int s_st;
    const int st = detect_stride(ei, &s_st);
    int e = blockIdx.x * blockDim.x + threadIdx.x;
    if (e < NEDGES) {
        int s = ei[(size_t)e * st];
        int d = ei[(size_t)NEDGES * st + (size_t)e * st];
        if ((unsigned)s < NNODES && (unsigned)d < NNODES) {
            int pos = atomicAdd(&g_off[d], 1);
            g_esrc[pos] = s;
        }
    }
}

// ---------------------------------------------------------------------------
// Tensor-core MLP: 2-term tf32 (A split hi/lo, B tf32 at staging).
//   D += alo*bhi ; D += ahi*bhi  — A effectively fp32, B truncated.
// H pre-split to (hi, lo) fragment regions in GEMM1 epilogue; GEMM2 inner
// loop has zero cvt work. h2 output written fp16.
// Fragment layouts (m16n8k8, A row-major, B col-major) — verified R11-R14.
// ---------------------------------------------------------------------------
__device__ __forceinline__ void split_tf32(float x, uint32_t& hi, uint32_t& lo) {
    asm("cvt.rna.tf32.f32 %0, %1;" : "=r"(hi) : "f"(x));
    float r = x - __uint_as_float(hi);
    asm("cvt.rna.tf32.f32 %0, %1;" : "=r"(lo) : "f"(r));
}
__device__ __forceinline__ uint32_t to_tf32(float x) {
    uint32_t r; asm("cvt.rna.tf32.f32 %0, %1;" : "=r"(r) : "f"(x)); return r;
}

__device__ __forceinline__ void mma_tf32(float* d, const uint32_t* a, uint32_t b0, uint32_t b1) {
    asm("mma.sync.aligned.m16n8k8.row.col.f32.tf32.tf32.f32 "
        "{%0,%1,%2,%3}, {%4,%5,%6,%7}, {%8,%9}, {%0,%1,%2,%3};"
        : "+f"(d[0]), "+f"(d[1]), "+f"(d[2]), "+f"(d[3])
        : "r"(a[0]), "r"(a[1]), "r"(a[2]), "r"(a[3]), "r"(b0), "r"(b1));
}

__global__ __launch_bounds__(MLP_THREADS, 1) void k_mlp(
    const float* __restrict__ X, const float* __restrict__ W1,
    const float* __restrict__ b1, const float* __restrict__ W2)
{
    extern __shared__ float sm[];
    float*    sXF   = sm;                        // 8mt x 8kt x 128       = 8192 f
    uint32_t* sW1F  = (uint32_t*)(sm + 8192);    // 8kt x 16nt x 64 u32   = 8192 u32
    uint32_t* sW2F  = sW1F + 8192;               // 16kt x 8nt x 64 u32   = 8192 u32
    uint32_t* sHFhi = sW2F + 8192;               // 8mt x 16kt x 128 u32  = 16384 u32
    uint32_t* sHFlo = sHFhi + 16384;             // 16384 u32
    float*    sb1   = (float*)(sHFlo + 16384);   // 128

    const int t    = threadIdx.x;
    const int lane = t & 31;
    const int w    = t >> 5;             // 16 warps
    const int g    = lane >> 2;          // 0..7
    const int tig  = lane & 3;           // 0..3
    const int mt   = w & 7;              // m-tile (both GEMMs)
    const int nh   = w >> 3;             // n-half (0/1)

    // ---- stage weights as tf32 into B-fragment layout (once) ----
    for (int i = t; i < IN_C * HID; i += MLP_THREADS) {       // W1 [k][n]
        int k = i >> 7, n = i & 127;
        int ln = (n & 7) * 4 + (k & 3);
        sW1F[(((k >> 3) * 16) + (n >> 3)) * 64 + ln * 2 + ((k & 7) >> 2)] = to_tf32(W1[i]);
    }
    for (int i = t; i < HID * OUT_C; i += MLP_THREADS) {      // W2 [k][n]
        int k = i >> 6, n = i & 63;
        int ln = (n & 7) * 4 + (k & 3);
        sW2F[(((k >> 3) * 8) + (n >> 3)) * 64 + ln * 2 + ((k & 7) >> 2)] = to_tf32(W2[i]);
    }
    if (t < HID) sb1[t] = b1[t];
    __syncthreads();

    for (int tile = blockIdx.x; tile < NTILES; tile += gridDim.x) {
        const int base = tile * NBT;

        // ---- stage X into A-fragment layout ----
        for (int i = t; i < NBT * IN_C / 4; i += MLP_THREADS) {
            int node = i >> 4, k0 = (i & 15) * 4;
            int gn = base + node;
            float4 v = make_float4(0.f, 0.f, 0.f, 0.f);
            if (gn < NNODES) v = *(const float4*)(X + (size_t)gn * IN_C + k0);
            int mtt = node >> 4, rr = node & 15;
            #pragma unroll
            for (int e = 0; e < 4; e++) {
                int k = k0 + e;
                float val = (e == 0) ? v.x : (e == 1) ? v.y : (e == 2) ? v.z : v.w;
                int cc = k & 7;
                int tb = (mtt * 8 + (k >> 3)) * 128;
                sXF[tb + ((rr & 7) * 4 + (cc & 3)) * 4 + ((rr >> 3) + 2 * (cc >> 2))] = val;
            }
        }
        __syncthreads();

        // ---- GEMM1: H = relu(X@W1 + b1); warp = mtile x 8 ntiles ----
        {
            float acc[8][4];
            #pragma unroll
            for (int j = 0; j < 8; j++) {
                float2 b = *(const float2*)&sb1[(nh * 8 + j) * 8 + tig * 2];
                acc[j][0] = b.x; acc[j][1] = b.y; acc[j][2] = b.x; acc[j][3] = b.y;
            }

            #pragma unroll 2
            for (int kt = 0; kt < 8; kt++) {
                float4 av = *(const float4*)&sXF[(mt * 8 + kt) * 128 + lane * 4];
                uint32_t ahi[4], alo[4];
                split_tf32(av.x, ahi[0], alo[0]);
                split_tf32(av.y, ahi[1], alo[1]);
                split_tf32(av.z, ahi[2], alo[2]);
                split_tf32(av.w, ahi[3], alo[3]);
                #pragma unroll
                for (int j = 0; j < 8; j++) {
                    uint2 bv = *(const uint2*)&sW1F[(kt * 16 + nh * 8 + j) * 64 + lane * 2];
                    mma_tf32(acc[j], alo, bv.x, bv.y);   // alo * bhi
                    mma_tf32(acc[j], ahi, bv.x, bv.y);   // ahi * bhi
                }
            }

            // relu + tf32-split + store into GEMM2 A-fragment hi/lo regions
            #pragma unroll
            for (int j = 0; j < 8; j++) {
                int kt2 = nh * 8 + j;
                int tb = (mt * 16 + kt2) * 128;
                int lane0 = g * 4 + 2 * (tig & 1);
                int idxb  = 2 * (tig >> 1);
                float r0 = fmaxf(acc[j][0], 0.f), r1 = fmaxf(acc[j][1], 0.f);
                float r2 = fmaxf(acc[j][2], 0.f), r3 = fmaxf(acc[j][3], 0.f);
                uint32_t h0,l0,h1,l1,h2,l2,h3,l3;
                split_tf32(r0, h0, l0); split_tf32(r1, h1, l1);
                split_tf32(r2, h2, l2); split_tf32(r3, h3, l3);
                *(uint2*)&sHFhi[tb + lane0 * 4 + idxb]       = make_uint2(h0, h2);
                *(uint2*)&sHFhi[tb + (lane0 + 1) * 4 + idxb] = make_uint2(h1, h3);
                *(uint2*)&sHFlo[tb + lane0 * 4 + idxb]       = make_uint2(l0, l2);
                *(uint2*)&sHFlo[tb + (lane0 + 1) * 4 + idxb] = make_uint2(l1, l3);
            }
        }
        __syncthreads();

        // ---- GEMM2: h2 = H @ W2; warp = mtile x 4 ntiles; no cvt in loop ----
        {
            float acc[4][4];
            #pragma unroll
            for (int j = 0; j < 4; j++)
                #pragma unroll
                for (int q = 0; q < 4; q++) acc[j][q] = 0.f;

            #pragma unroll 4
            for (int kt = 0; kt < 16; kt++) {
                uint4 hv = *(const uint4*)&sHFhi[(mt * 16 + kt) * 128 + lane * 4];
                uint4 lv = *(const uint4*)&sHFlo[(mt * 16 + kt) * 128 + lane * 4];
                uint32_t ahi[4] = {hv.x, hv.y, hv.z, hv.w};
                uint32_t alo[4] = {lv.x, lv.y, lv.z, lv.w};
                #pragma unroll
                for (int j = 0; j < 4; j++) {
                    uint2 bv = *(const uint2*)&sW2F[(kt * 8 + nh * 4 + j) * 64 + lane * 2];
                    mma_tf32(acc[j], alo, bv.x, bv.y);
                    mma_tf32(acc[j], ahi, bv.x, bv.y);
                }
            }

            #pragma unroll
            for (int j = 0; j < 4; j++) {
                int col = (nh * 4 + j) * 8 + tig * 2;   // even
                int gn0 = base + mt * 16 + g;
                int gn1 = gn0 + 8;
                __half2 p01 = __floats2half2_rn(acc[j][0], acc[j][1]);
                __half2 p23 = __floats2half2_rn(acc[j][2], acc[j][3]);
                if (gn0 < NNODES)
                    ((__half2*)g_h2)[(size_t)gn0 * (OUT_C / 2) + (col >> 1)] = p01;
                if (gn1 < NNODES)
                    ((__half2*)g_h2)[(size_t)gn1 * (OUT_C / 2) + (col >> 1)] = p23;
            }
        }
        __syncthreads();
    }
}

// ---------------------------------------------------------------------------
// Pull aggregation: one warp per dst node, lane owns a half2 column chunk.
// 4-deep software pipeline: 4 independent index loads, then 4 dinv + 4 row
// gathers in flight (MLP=4 on the 2-level dependent chain).
// ---------------------------------------------------------------------------
__global__ __launch_bounds__(256) void k_pull(
    const float* __restrict__ b2, float* __restrict__ out)
{
    const int warp = (blockIdx.x * blockDim.x + threadIdx.x) >> 5;
    const int lane = threadIdx.x & 31;
    if (warp >= NNODES) return;
    const int n = warp;

    const __half2* __restrict__ tab = (const __half2*)g_h2;
    const float din = g_dinv[n];

    float2 self = __half22float2(tab[(size_t)n * (OUT_C / 2) + lane]);
    float2 acc;
    acc.x = din * self.x;
    acc.y = din * self.y;
    float2 acc2 = make_float2(0.f, 0.f);   // second accumulator for ILP

    const int deg = g_degi[n];
    const int end = g_off[n];
    const int beg = end - deg;

    int i = beg;
    for (; i + 3 < end; i += 4) {
        const int s0 = __ldg(&g_esrc[i]);
        const int s1 = __ldg(&g_esrc[i + 1]);
        const int s2 = __ldg(&g_esrc[i + 2]);
        const int s3 = __ldg(&g_esrc[i + 3]);
        const float d0 = __ldg(&g_dinv[s0]);
        const float d1 = __ldg(&g_dinv[s1]);
        const float d2 = __ldg(&g_dinv[s2]);
        const float d3 = __ldg(&g_dinv[s3]);
        float2 v0 = __half22float2(tab[(size_t)s0 * (OUT_C / 2) + lane]);
        float2 v1 = __half22float2(tab[(size_t)s1 * (OUT_C / 2) + lane]);
        float2 v2 = __half22float2(tab[(size_t)s2 * (OUT_C / 2) + lane]);
        float2 v3 = __half22float2(tab[(size_t)s3 * (OUT_C / 2) + lane]);
        acc.x  = fmaf(d0, v0.x, acc.x);
        acc.y  = fmaf(d0, v0.y, acc.y);
        acc2.x = fmaf(d1, v1.x, acc2.x);
        acc2.y = fmaf(d1, v1.y, acc2.y);
        acc.x  = fmaf(d2, v2.x, acc.x);
        acc.y  = fmaf(d2, v2.y, acc.y);
        acc2.x = fmaf(d3, v3.x, acc2.x);
        acc2.y = fmaf(d3, v3.y, acc2.y);
    }
    for (; i < end; i++) {
        const int s = __ldg(&g_esrc[i]);
        const float ds = __ldg(&g_dinv[s]);
        float2 v = __half22float2(tab[(size_t)s * (OUT_C / 2) + lane]);
        acc.x = fmaf(ds, v.x, acc.x);
        acc.y = fmaf(ds, v.y, acc.y);
    }
    acc.x += acc2.x;
    acc.y += acc2.y;

    const float2 bb = ((const float2*)b2)[lane];
    float2 o;
    o.x = fmaf(din, acc.x, bb.x);
    o.y = fmaf(din, acc.y, bb.y);
    ((float2*)out)[(size_t)n * (OUT_C / 2) + lane] = o;
}

// ---------------------------------------------------------------------------
extern "C" void kernel_launch(void* const* d_in, const int* in_sizes, int n_in,
                              void* d_out, int out_size)
{
    const float* X   = (const float*)d_in[0];
    const int*   ei  = (const int*)d_in[1];
    const float* W1  = (const float*)d_in[2];
    const float* b1  = (const float*)d_in[3];
    const float* W2  = (const float*)d_in[4];
    const float* b2  = (const float*)d_in[5];
    float*       out = (float*)d_out;

    const int smem_bytes = (8192 + 8192 + 8192 + 16384 + 16384 + 128) * 4; // 229,888 B

    static cudaStream_t s1;
    static cudaEvent_t evRoot, evMlp;
    static void *p_degi;
    static int init_done = 0;
    if (!init_done) {
        cudaFuncSetAttribute(k_mlp, cudaFuncAttributeMaxDynamicSharedMemorySize, smem_bytes);
        cudaStreamCreateWithFlags(&s1, cudaStreamNonBlocking);
        cudaEventCreateWithFlags(&evRoot, cudaEventDisableTiming);
        cudaEventCreateWithFlags(&evMlp, cudaEventDisableTiming);
        cudaGetSymbolAddress(&p_degi, g_degi);
        init_done = 1;
    }

    cudaEventRecord(evRoot, 0);

    // Critical chain on the capture (legacy) stream.
    cudaMemsetAsync(p_degi, 0, NNODES * sizeof(int), 0);
    k_deg_count<<<(NEDGES + 255) / 256, 256>>>(ei);   // also zeroes scan states
    k_scan     <<<SCAN_NB, SCAN_BLK>>>();
    k_scatter  <<<(NEDGES + 255) / 256, 256>>>(ei);

    // Fork: MLP depends only on the root.
    cudaStreamWaitEvent(s1, evRoot, 0);
    k_mlp<<<148, MLP_THREADS, smem_bytes, s1>>>(X, W1, b1, W2);
    cudaEventRecord(evMlp, s1);

    // Join, then pull.
    cudaStreamWaitEvent(0, evMlp, 0);
    k_pull     <<<(NNODES * 32 + 255) / 256, 256>>>(b2, out);
}

// round 16
// speedup vs baseline: 1.2895x; 1.2895x over previous
#include <cuda_runtime.h>
#include <cuda_fp16.h>
#include <cstdint>

#define NNODES 100000
#define NEDGES 1600000
#define IN_C 64
#define HID 128
#define OUT_C 64
#define NBT 128            // nodes per MLP tile
#define NTILES ((NNODES + NBT - 1) / NBT)   // 782
#define MLP_THREADS 512
#define SCAN_BLK 1024
#define SCAN_NB ((NNODES + SCAN_BLK - 1) / SCAN_BLK)

// Scratch (static device arrays; heap alloc is forbidden)
__device__ __align__(16) __half g_h2[(size_t)NNODES * OUT_C]; // fp16 h2 table, 12.8 MB
__device__ float g_dinv[NNODES];
__device__ int   g_degi[NNODES];
__device__ int   g_off[NNODES];      // CSR offsets; scatter bumps them to 'end'
__device__ int   g_esrc[NEDGES];
__device__ unsigned long long g_scanstate[SCAN_NB];

// ---------------------------------------------------------------------------
__device__ __forceinline__ int detect_stride(const int* __restrict__ ei, int* s_st) {
    if (threadIdx.x < 32) {
        int z = (ei[2 * threadIdx.x + 1] == 0);
        unsigned m = __ballot_sync(0xFFFFFFFFu, z);
        if (threadIdx.x == 0) *s_st = (m == 0xFFFFFFFFu) ? 2 : 1;
    }
    __syncthreads();
    return *s_st;
}

__global__ __launch_bounds__(256) void k_deg_count(const int* __restrict__ ei) {
    __shared__ int s_st;
    const int st = detect_stride(ei, &s_st);
    int e = blockIdx.x * blockDim.x + threadIdx.x;
    if (e < NEDGES) {
        int d = ei[(size_t)NEDGES * st + (size_t)e * st];
        if ((unsigned)d < NNODES) atomicAdd(&g_degi[d], 1);
    }
}

__global__ __launch_bounds__(SCAN_BLK) void k_scan() {
    __shared__ int wsum[32];
    __shared__ int s_total, s_prefix;
    const int t = threadIdx.x;
    const int bid = blockIdx.x;
    const int i = bid * SCAN_BLK + t;
    const int v = (i < NNODES) ? g_degi[i] : 0;
    if (i < NNODES) g_dinv[i] = rsqrtf((float)(v + 1));

    int x = v;
    #pragma unroll
    for (int o = 1; o < 32; o <<= 1) {
        int y = __shfl_up_sync(0xFFFFFFFFu, x, o);
        if ((t & 31) >= o) x += y;
    }
    if ((t & 31) == 31) wsum[t >> 5] = x;
    __syncthreads();
    if (t < 32) {
        int w = wsum[t];
        int xx = w;
        #pragma unroll
        for (int o = 1; o < 32; o <<= 1) {
            int y = __shfl_up_sync(0xFFFFFFFFu, xx, o);
            if (t >= o) xx += y;
        }
        wsum[t] = xx - w;
        if (t == 31) s_total = xx;
    }
    __syncthreads();

    if (t == 0) {
        unsigned long long flag = (bid == 0) ? 2ULL : 1ULL;
        __threadfence();
        *(volatile unsigned long long*)&g_scanstate[bid] =
            (flag << 32) | (unsigned)s_total;
        if (bid == 0) s_prefix = 0;
    }

    if (bid > 0 && t < 32) {
        int running = 0;
        int base = bid - 1;
        for (;;) {
            int j = base - t;
            unsigned long long s;
            if (j >= 0) {
                do { s = *(volatile unsigned long long*)&g_scanstate[j]; }
                while ((s >> 32) == 0);
            } else {
                s = (2ULL << 32);
            }
            int flag = (int)(s >> 32);
            int val  = (int)(s & 0xFFFFFFFFu);
            unsigned pmask = __ballot_sync(0xFFFFFFFFu, flag == 2);
            if (pmask) {
                int stop = __ffs(pmask) - 1;
                int contrib = (t <= stop) ? val : 0;
                #pragma unroll
                for (int o = 16; o >= 1; o >>= 1)
                    contrib += __shfl_down_sync(0xFFFFFFFFu, contrib, o);
                running += __shfl_sync(0xFFFFFFFFu, contrib, 0);
                break;
            } else {
                int contrib = val;
                #pragma unroll
                for (int o = 16; o >= 1; o >>= 1)
                    contrib += __shfl_down_sync(0xFFFFFFFFu, contrib, o);
                running += __shfl_sync(0xFFFFFFFFu, contrib, 0);
                base -= 32;
            }
        }
        if (t == 0) {
            __threadfence();
            *(volatile unsigned long long*)&g_scanstate[bid] =
                (2ULL << 32) | (unsigned)(running + s_total);
            s_prefix = running;
        }
    }
    __syncthreads();

    if (i < NNODES) g_off[i] = (x - v + wsum[t >> 5]) + s_prefix;
}

__global__ __launch_bounds__(256) void k_scatter(const int* __restrict__ ei) {
    __shared__ int s_st;
    const int st = detect_stride(ei, &s_st);
    int e = blockIdx.x * blockDim.x + threadIdx.x;
    if (e < NEDGES) {
        int s = ei[(size_t)e * st];
        int d = ei[(size_t)NEDGES * st + (size_t)e * st];
        if ((unsigned)s < NNODES && (unsigned)d < NNODES) {
            int pos = atomicAdd(&g_off[d], 1);
            g_esrc[pos] = s;
        }
    }
}

// ---------------------------------------------------------------------------
// Tensor-core MLP on m16n8k16 fp16 MMA, fp32 accumulate.
// Accuracy: B (weights) fp16-rounded = same 11-bit mantissa as tf32 (R13/14
// measured 2.5e-4). A kept effectively fp32 via 2-term hi/lo fp16 split:
//   D += alo*b ; D += ahi*b.
// ALL conversions happen at staging time; inner loops are LDS+MMA only.
// fp16 m16n8k16 fragment maps:
//   A value (r,c): reg=(c>>3)*2+(r>>3), lane=(r&7)*4+((c&7)>>1), half=c&1
//   B value (k,n): reg=k>>3, lane=n*4+((k&7)>>1), half=k&1
//   C value: c0=(g,2t) c1=(g,2t+1) c2=(g+8,2t) c3=(g+8,2t+1); g=lane>>2,t=lane&3
// ---------------------------------------------------------------------------
__device__ __forceinline__ void mma_f16(float* d, const uint32_t* a, uint32_t b0, uint32_t b1) {
    asm("mma.sync.aligned.m16n8k16.row.col.f32.f16.f16.f32 "
        "{%0,%1,%2,%3}, {%4,%5,%6,%7}, {%8,%9}, {%0,%1,%2,%3};"
        : "+f"(d[0]), "+f"(d[1]), "+f"(d[2]), "+f"(d[3])
        : "r"(a[0]), "r"(a[1]), "r"(a[2]), "r"(a[3]), "r"(b0), "r"(b1));
}

__device__ __forceinline__ void split_h2(float a, float b, uint32_t& hi, uint32_t& lo) {
    __half ha = __float2half_rn(a), hb = __float2half_rn(b);
    __half la = __float2half_rn(a - __half2float(ha));
    __half lb = __float2half_rn(b - __half2float(hb));
    __half2 h = __halves2half2(ha, hb), l = __halves2half2(la, lb);
    hi = *(uint32_t*)&h;
    lo = *(uint32_t*)&l;
}

__global__ __launch_bounds__(MLP_THREADS, 1) void k_mlp(
    const float* __restrict__ X, const float* __restrict__ W1,
    const float* __restrict__ b1, const float* __restrict__ W2)
{
    extern __shared__ uint32_t smu[];
    uint32_t* sXFhi = smu;                 // 8mt x 4kt x 128 = 4096 u32
    uint32_t* sXFlo = sXFhi + 4096;        // 4096
    uint32_t* sW1F  = sXFlo + 4096;        // 4kt x 16nt x 64 = 4096
    uint32_t* sW2F  = sW1F + 4096;         // 8kt x 8nt x 64  = 4096
    uint32_t* sHFhi = sW2F + 4096;         // 8mt x 8kt x 128 = 8192
    uint32_t* sHFlo = sHFhi + 8192;        // 8192
    float*    sb1   = (float*)(sHFlo + 8192);  // 128

    const int t    = threadIdx.x;
    const int lane = t & 31;
    const int w    = t >> 5;             // 16 warps
    const int g    = lane >> 2;          // 0..7
    const int tig  = lane & 3;           // 0..3
    const int mt   = w & 7;              // m-tile (both GEMMs)
    const int nh   = w >> 3;             // n-half (0/1)

    // ---- stage W1 as fp16 B-fragments (k-pairs per thread; no RMW) ----
    for (int i = t; i < IN_C * HID / 2; i += MLP_THREADS) {
        int kp = i >> 7, n = i & 127;        // k0 = 2*kp
        int k0 = kp * 2;
        float w0 = W1[(size_t)k0 * HID + n];
        float w1 = W1[(size_t)(k0 + 1) * HID + n];
        __half2 h = __halves2half2(__float2half_rn(w0), __float2half_rn(w1));
        int kt = k0 >> 4, nt = n >> 3, cc = k0 & 15;
        int ln = (n & 7) * 4 + ((cc & 7) >> 1);
        sW1F[(kt * 16 + nt) * 64 + ln * 2 + (cc >> 3)] = *(uint32_t*)&h;
    }
    // ---- stage W2 ----
    for (int i = t; i < HID * OUT_C / 2; i += MLP_THREADS) {
        int kp = i >> 6, n = i & 63;
        int k0 = kp * 2;
        float w0 = W2[(size_t)k0 * OUT_C + n];
        float w1 = W2[(size_t)(k0 + 1) * OUT_C + n];
        __half2 h = __halves2half2(__float2half_rn(w0), __float2half_rn(w1));
        int kt = k0 >> 4, nt = n >> 3, cc = k0 & 15;
        int ln = (n & 7) * 4 + ((cc & 7) >> 1);
        sW2F[(kt * 8 + nt) * 64 + ln * 2 + (cc >> 3)] = *(uint32_t*)&h;
    }
    if (t < HID) sb1[t] = b1[t];
    __syncthreads();

    for (int tile = blockIdx.x; tile < NTILES; tile += gridDim.x) {
        const int base = tile * NBT;

        // ---- stage X into hi/lo fp16 A-fragments ----
        for (int i = t; i < NBT * IN_C / 4; i += MLP_THREADS) {
            int node = i >> 4, k0 = (i & 15) * 4;
            int gn = base + node;
            float4 v = make_float4(0.f, 0.f, 0.f, 0.f);
            if (gn < NNODES) v = *(const float4*)(X + (size_t)gn * IN_C + k0);
            uint32_t h01, l01, h23, l23;
            split_h2(v.x, v.y, h01, l01);
            split_h2(v.z, v.w, h23, l23);
            int rr = node & 15;
            int tb = ((node >> 4) * 4 + (k0 >> 4)) * 128;
            int reg = ((k0 & 15) >> 3) * 2 + (rr >> 3);
            int ln01 = (rr & 7) * 4 + ((k0 & 7) >> 1);
            sXFhi[tb + ln01 * 4 + reg]       = h01;
            sXFhi[tb + (ln01 + 1) * 4 + reg] = h23;
            sXFlo[tb + ln01 * 4 + reg]       = l01;
            sXFlo[tb + (ln01 + 1) * 4 + reg] = l23;
        }
        __syncthreads();

        // ---- GEMM1: H = relu(X@W1 + b1); warp = mtile x 8 ntiles ----
        {
            float acc[8][4];
            #pragma unroll
            for (int j = 0; j < 8; j++) {
                float2 b = *(const float2*)&sb1[(nh * 8 + j) * 8 + tig * 2];
                acc[j][0] = b.x; acc[j][1] = b.y; acc[j][2] = b.x; acc[j][3] = b.y;
            }

            #pragma unroll
            for (int kt = 0; kt < 4; kt++) {
                uint4 hv = *(const uint4*)&sXFhi[(mt * 4 + kt) * 128 + lane * 4];
                uint4 lv = *(const uint4*)&sXFlo[(mt * 4 + kt) * 128 + lane * 4];
                uint32_t ah[4] = {hv.x, hv.y, hv.z, hv.w};
                uint32_t al[4] = {lv.x, lv.y, lv.z, lv.w};
                #pragma unroll
                for (int j = 0; j < 8; j++) {
                    uint2 bv = *(const uint2*)&sW1F[(kt * 16 + nh * 8 + j) * 64 + lane * 2];
                    mma_f16(acc[j], al, bv.x, bv.y);
                    mma_f16(acc[j], ah, bv.x, bv.y);
                }
            }

            // relu + fp16 hi/lo split + store into GEMM2 A-fragment layout.
            // Thread writes its OWN lane's words: regs (j&1)*2, +1 -> one uint2.
            #pragma unroll
            for (int j = 0; j < 8; j++) {
                float r0 = fmaxf(acc[j][0], 0.f), r1 = fmaxf(acc[j][1], 0.f);
                float r2 = fmaxf(acc[j][2], 0.f), r3 = fmaxf(acc[j][3], 0.f);
                uint32_t h01, l01, h23, l23;
                split_h2(r0, r1, h01, l01);
                split_h2(r2, r3, h23, l23);
                int kt2 = (nh * 8 + j) >> 1;
                int widx = (mt * 8 + kt2) * 128 + lane * 4 + (j & 1) * 2;
                *(uint2*)&sHFhi[widx] = make_uint2(h01, h23);
                *(uint2*)&sHFlo[widx] = make_uint2(l01, l23);
            }
        }
        __syncthreads();

        // ---- GEMM2: h2 = H @ W2; warp = mtile x 4 ntiles ----
        {
            float acc[4][4];
            #pragma unroll
            for (int j = 0; j < 4; j++)
                #pragma unroll
                for (int q = 0; q < 4; q++) acc[j][q] = 0.f;

            #pragma unroll
            for (int kt = 0; kt < 8; kt++) {
                uint4 hv = *(const uint4*)&sHFhi[(mt * 8 + kt) * 128 + lane * 4];
                uint4 lv = *(const uint4*)&sHFlo[(mt * 8 + kt) * 128 + lane * 4];
                uint32_t ah[4] = {hv.x, hv.y, hv.z, hv.w};
                uint32_t al[4] = {lv.x, lv.y, lv.z, lv.w};
                #pragma unroll
                for (int j = 0; j < 4; j++) {
                    uint2 bv = *(const uint2*)&sW2F[(kt * 8 + nh * 4 + j) * 64 + lane * 2];
                    mma_f16(acc[j], al, bv.x, bv.y);
                    mma_f16(acc[j], ah, bv.x, bv.y);
                }
            }

            #pragma unroll
            for (int j = 0; j < 4; j++) {
                int col = (nh * 4 + j) * 8 + tig * 2;
                int gn0 = base + mt * 16 + g;
                int gn1 = gn0 + 8;
                __half2 p01 = __floats2half2_rn(acc[j][0], acc[j][1]);
                __half2 p23 = __floats2half2_rn(acc[j][2], acc[j][3]);
                if (gn0 < NNODES)
                    ((__half2*)g_h2)[(size_t)gn0 * (OUT_C / 2) + (col >> 1)] = p01;
                if (gn1 < NNODES)
                    ((__half2*)g_h2)[(size_t)gn1 * (OUT_C / 2) + (col >> 1)] = p23;
            }
        }
        __syncthreads();
    }
}

// ---------------------------------------------------------------------------
// Pull aggregation (R14 form): one warp per dst node, 2-edge unroll.
// ---------------------------------------------------------------------------
__global__ __launch_bounds__(256) void k_pull(
    const float* __restrict__ b2, float* __restrict__ out)
{
    const int warp = (blockIdx.x * blockDim.x + threadIdx.x) >> 5;
    const int lane = threadIdx.x & 31;
    if (warp >= NNODES) return;
    const int n = warp;

    const __half2* __restrict__ tab = (const __half2*)g_h2;
    const float din = g_dinv[n];

    float2 self = __half22float2(tab[(size_t)n * (OUT_C / 2) + lane]);
    float2 acc;
    acc.x = din * self.x;
    acc.y = din * self.y;

    const int deg = g_degi[n];
    const int end = g_off[n];
    const int beg = end - deg;

    int i = beg;
    for (; i + 1 < end; i += 2) {
        const int s0 = __ldg(&g_esrc[i]);
        const int s1 = __ldg(&g_esrc[i + 1]);
        const float d0 = g_dinv[s0];
        const float d1 = g_dinv[s1];
        float2 v0 = __half22float2(tab[(size_t)s0 * (OUT_C / 2) + lane]);
        float2 v1 = __half22float2(tab[(size_t)s1 * (OUT_C / 2) + lane]);
        acc.x = fmaf(d0, v0.x, acc.x);
        acc.y = fmaf(d0, v0.y, acc.y);
        acc.x = fmaf(d1, v1.x, acc.x);
        acc.y = fmaf(d1, v1.y, acc.y);
    }
    if (i < end) {
        const int s = __ldg(&g_esrc[i]);
        const float ds = g_dinv[s];
        float2 v = __half22float2(tab[(size_t)s * (OUT_C / 2) + lane]);
        acc.x = fmaf(ds, v.x, acc.x);
        acc.y = fmaf(ds, v.y, acc.y);
    }

    const float2 bb = ((const float2*)b2)[lane];
    float2 o;
    o.x = fmaf(din, acc.x, bb.x);
    o.y = fmaf(din, acc.y, bb.y);
    ((float2*)out)[(size_t)n * (OUT_C / 2) + lane] = o;
}

// ---------------------------------------------------------------------------
extern "C" void kernel_launch(void* const* d_in, const int* in_sizes, int n_in,
                              void* d_out, int out_size)
{
    const float* X   = (const float*)d_in[0];
    const int*   ei  = (const int*)d_in[1];
    const float* W1  = (const float*)d_in[2];
    const float* b1  = (const float*)d_in[3];
    const float* W2  = (const float*)d_in[4];
    const float* b2  = (const float*)d_in[5];
    float*       out = (float*)d_out;

    const int smem_bytes = (4096*2 + 4096 + 4096 + 8192*2) * 4 + 128 * 4; // 131,584 B

    static cudaStream_t s1;
    static cudaEvent_t evRoot, evMlp;
    static void *p_degi, *p_state;
    static int init_done = 0;
    if (!init_done) {
        cudaFuncSetAttribute(k_mlp, cudaFuncAttributeMaxDynamicSharedMemorySize, smem_bytes);
        cudaStreamCreateWithFlags(&s1, cudaStreamNonBlocking);
        cudaEventCreateWithFlags(&evRoot, cudaEventDisableTiming);
        cudaEventCreateWithFlags(&evMlp, cudaEventDisableTiming);
        cudaGetSymbolAddress(&p_degi, g_degi);
        cudaGetSymbolAddress(&p_state, g_scanstate);
        init_done = 1;
    }

    cudaEventRecord(evRoot, 0);

    // Critical chain on the capture (legacy) stream.
    cudaMemsetAsync(p_degi, 0, NNODES * sizeof(int), 0);
    cudaMemsetAsync(p_state, 0, SCAN_NB * sizeof(unsigned long long), 0);
    k_deg_count<<<(NEDGES + 255) / 256, 256>>>(ei);
    k_scan     <<<SCAN_NB, SCAN_BLK>>>();
    k_scatter  <<<(NEDGES + 255) / 256, 256>>>(ei);

    // Fork: MLP depends only on the root.
    cudaStreamWaitEvent(s1, evRoot, 0);
    k_mlp<<<148, MLP_THREADS, smem_bytes, s1>>>(X, W1, b1, W2);
    cudaEventRecord(evMlp, s1);

    // Join, then pull.
    cudaStreamWaitEvent(0, evMlp, 0);
    k_pull     <<<(NNODES * 32 + 255) / 256, 256>>>(b2, out);
}